// round 1
// baseline (speedup 1.0000x reference)
#include <cuda_runtime.h>
#include <math.h>

#define VOCAB  50000
#define EMBED  300
#define HIDDEN 512
#define BATCH  64
#define SEQ    128
#define GATES  2048   // 4*HIDDEN

#define NCTA 128
#define NTHR 256
#define HSP  516      // padded smem row stride (floats) for h tile
#define ZSP  20       // padded smem row stride for gate exchange

// ---------------- persistent device scratch (allowed: __device__ globals) ----
__device__ __align__(16) float g_xproj[(size_t)SEQ * BATCH * GATES]; // 64 MB
__device__ __align__(16) float g_h0[2][BATCH * HIDDEN];
__device__ __align__(16) float g_h1[2][BATCH * HIDDEN];
__device__ unsigned g_bar_count;
__device__ unsigned g_bar_gen;

// ---------------- helpers ----------------------------------------------------
__device__ __forceinline__ float sigf(float x) { return 1.0f / (1.0f + __expf(-x)); }

__device__ __forceinline__ void grid_barrier(unsigned nb)
{
    __syncthreads();
    if (threadIdx.x == 0) {
        __threadfence();                                   // release my writes
        unsigned gen = *((volatile unsigned*)&g_bar_gen);  // read sense BEFORE arrival
        unsigned t   = atomicAdd(&g_bar_count, 1u);
        if (t == nb - 1u) {
            g_bar_count = 0u;
            __threadfence();
            atomicAdd(&g_bar_gen, 1u);                     // release
        } else {
            while (*((volatile unsigned*)&g_bar_gen) == gen) { }
        }
        __threadfence();                                   // acquire
    }
    __syncthreads();
}

// Load full h state [64 x 512] into smem tile hs[b][k] (stride HSP).
// MUST bypass L1 (__ldcg): h buffers are rewritten by other CTAs every 2 steps.
__device__ __forceinline__ void load_hs(float* hs, const float* __restrict__ src)
{
    const float4* s4 = (const float4*)src;
    for (int i = threadIdx.x; i < BATCH * (HIDDEN / 4); i += NTHR) {
        int bb = i >> 7, k4 = i & 127;
        float4 v = __ldcg(s4 + i);
        *(float4*)(hs + bb * HSP + k4 * 4) = v;
    }
}

// Load 512 rows of W (starting at Wbase) for this CTA's 16 gate columns:
// cols {q*512 + 4g .. +3} for q=0..3.  ws layout: ws[k*16 + q*4 + u].
__device__ __forceinline__ void load_ws(float* ws, const float* __restrict__ Wbase, int g)
{
    float4* w4 = (float4*)ws;
    for (int i = threadIdx.x; i < 512 * 4; i += NTHR) {
        int k = i >> 2, q = i & 3;
        w4[k * 4 + q] = __ldg((const float4*)(Wbase + (size_t)k * GATES + q * 512) + g);
    }
}

// acc[0..3] += sum_k hrow[k] * W[k][col0..col0+3]   (one gate group cg)
__device__ __forceinline__ void gemm512(float* a0, float* a1, float* a2, float* a3,
                                        const float* hrow, const float4* w4, int cg)
{
    float r0 = *a0, r1 = *a1, r2 = *a2, r3 = *a3;
#pragma unroll 8
    for (int k = 0; k < 512; k += 4) {
        float4 hv = *(const float4*)(hrow + k);
        float4 w0 = w4[(k + 0) * 4 + cg];
        float4 w1 = w4[(k + 1) * 4 + cg];
        float4 w2 = w4[(k + 2) * 4 + cg];
        float4 w3 = w4[(k + 3) * 4 + cg];
        r0 = fmaf(hv.x, w0.x, r0); r1 = fmaf(hv.x, w0.y, r1);
        r2 = fmaf(hv.x, w0.z, r2); r3 = fmaf(hv.x, w0.w, r3);
        r0 = fmaf(hv.y, w1.x, r0); r1 = fmaf(hv.y, w1.y, r1);
        r2 = fmaf(hv.y, w1.z, r2); r3 = fmaf(hv.y, w1.w, r3);
        r0 = fmaf(hv.z, w2.x, r0); r1 = fmaf(hv.z, w2.y, r1);
        r2 = fmaf(hv.z, w2.z, r2); r3 = fmaf(hv.z, w2.w, r3);
        r0 = fmaf(hv.w, w3.x, r0); r1 = fmaf(hv.w, w3.y, r1);
        r2 = fmaf(hv.w, w3.z, r2); r3 = fmaf(hv.w, w3.w, r3);
    }
    *a0 = r0; *a1 = r1; *a2 = r2; *a3 = r3;
}

// ---------------- phase 1: xproj[t][b][:] = emb[x[b,t]] @ W0[0:300,:] --------
#define PK 20
__global__ void __launch_bounds__(256) xproj_kernel(const int* __restrict__ x,
                                                    const float* __restrict__ emb,
                                                    const float* __restrict__ W0)
{
    __shared__ float Ast[PK][68];  // A^T tile: [k][m]
    __shared__ float Bs[PK][68];   // B tile:   [k][n]
    __shared__ int   toks[64];

    const int rb  = blockIdx.x * 64;   // row = t*64 + b
    const int cb  = blockIdx.y * 64;
    const int tid = threadIdx.x;

    if (tid < 64) {
        int r = rb + tid;
        toks[tid] = x[(r & 63) * SEQ + (r >> 6)];
    }
    __syncthreads();

    const int ty = tid >> 4, tx = tid & 15;
    float c[4][4] = {};

    for (int e0 = 0; e0 < EMBED; e0 += PK) {
        for (int i = tid; i < 64 * PK; i += 256) {
            int m = i / PK, e = i - m * PK;
            Ast[e][m] = emb[(size_t)toks[m] * EMBED + e0 + e];
        }
        for (int i = tid; i < PK * 64; i += 256) {
            int e = i >> 6, n = i & 63;
            Bs[e][n] = W0[(size_t)(e0 + e) * GATES + cb + n];
        }
        __syncthreads();
#pragma unroll
        for (int k = 0; k < PK; k++) {
            float4 av = *(const float4*)&Ast[k][ty * 4];
            float4 bv = *(const float4*)&Bs[k][tx * 4];
            c[0][0] = fmaf(av.x, bv.x, c[0][0]); c[0][1] = fmaf(av.x, bv.y, c[0][1]);
            c[0][2] = fmaf(av.x, bv.z, c[0][2]); c[0][3] = fmaf(av.x, bv.w, c[0][3]);
            c[1][0] = fmaf(av.y, bv.x, c[1][0]); c[1][1] = fmaf(av.y, bv.y, c[1][1]);
            c[1][2] = fmaf(av.y, bv.z, c[1][2]); c[1][3] = fmaf(av.y, bv.w, c[1][3]);
            c[2][0] = fmaf(av.z, bv.x, c[2][0]); c[2][1] = fmaf(av.z, bv.y, c[2][1]);
            c[2][2] = fmaf(av.z, bv.z, c[2][2]); c[2][3] = fmaf(av.z, bv.w, c[2][3]);
            c[3][0] = fmaf(av.w, bv.x, c[3][0]); c[3][1] = fmaf(av.w, bv.y, c[3][1]);
            c[3][2] = fmaf(av.w, bv.z, c[3][2]); c[3][3] = fmaf(av.w, bv.w, c[3][3]);
        }
        __syncthreads();
    }
#pragma unroll
    for (int ii = 0; ii < 4; ii++) {
        size_t row = (size_t)(rb + ty * 4 + ii);
        *(float4*)(g_xproj + row * GATES + cb + tx * 4) =
            make_float4(c[ii][0], c[ii][1], c[ii][2], c[ii][3]);
    }
}

// ---------------- phase 2: persistent recurrent kernel -----------------------
// CTA g owns hidden units 4g..4g+3 (both layers).  Thread tid = b*4 + cg:
// computes gate cg (cols cg*512 + 4g .. +3) for batch b.
#define SMEM_FLOATS (BATCH * HSP + 512 * 16 + BATCH * ZSP + 2 * BATCH * 4)
#define SMEM_BYTES  (SMEM_FLOATS * 4)

__global__ void __launch_bounds__(NTHR, 1) lstm_persistent(
    const float* __restrict__ W0,  const float* __restrict__ b0,
    const float* __restrict__ W1,  const float* __restrict__ b1,
    const float* __restrict__ Wd,  const float* __restrict__ bd,
    const float* __restrict__ Wpe, const float* __restrict__ bpe,
    const float* __restrict__ Wbur,const float* __restrict__ bbur,
    float* __restrict__ out)
{
    extern __shared__ float sm[];
    float* hs = sm;                      // [64][HSP]
    float* ws = hs + BATCH * HSP;        // [512][16]
    float* zs = ws + 512 * 16;           // [64][ZSP]
    float* cs = zs + BATCH * ZSP;        // c0 [64*4] then c1 [64*4]

    const int g   = blockIdx.x;
    const int tid = threadIdx.x;
    const int b   = tid >> 2, cg = tid & 3;

    // init: zero cell state + phase-0 h buffers
    for (int i = tid; i < 2 * BATCH * 4; i += NTHR) cs[i] = 0.0f;
    for (int i = g * NTHR + tid; i < BATCH * HIDDEN; i += NCTA * NTHR) {
        g_h0[0][i] = 0.0f;
        g_h1[0][i] = 0.0f;
    }
    grid_barrier(NCTA);

    const int col0 = cg * 512 + 4 * g;
    const float4 bias0 = *(const float4*)(b0 + col0);
    const float4 bias1 = *(const float4*)(b1 + col0);
    const float4* ws4 = (const float4*)ws;

    for (int t = 0; t < SEQ; t++) {
        const int p = t & 1;

        // ======== layer 0: z0 = xproj[t] + h0_prev @ W0[300:,:] + b0 ========
        load_hs(hs, g_h0[p]);
        load_ws(ws, W0 + (size_t)EMBED * GATES, g);
        __syncthreads();

        float4 xp = *(const float4*)(g_xproj + ((size_t)t * BATCH + b) * GATES + col0);
        float a0 = bias0.x + xp.x, a1 = bias0.y + xp.y;
        float a2 = bias0.z + xp.z, a3 = bias0.w + xp.w;
        gemm512(&a0, &a1, &a2, &a3, hs + b * HSP, ws4, cg);

        zs[b * ZSP + cg * 4 + 0] = a0;
        zs[b * ZSP + cg * 4 + 1] = a1;
        zs[b * ZSP + cg * 4 + 2] = a2;
        zs[b * ZSP + cg * 4 + 3] = a3;
        __syncthreads();
        {   // cell update (layer 0): tid = bb*4 + u
            const int bb = tid >> 2, u = tid & 3;
            float zi = zs[bb * ZSP +      u];
            float zj = zs[bb * ZSP +  4 + u];
            float zf = zs[bb * ZSP +  8 + u];
            float zo = zs[bb * ZSP + 12 + u];
            float c  = cs[tid];
            float cn = c * sigf(zf + 1.0f) + sigf(zi) * tanhf(zj);
            float hn = tanhf(cn) * sigf(zo);
            cs[tid] = cn;
            g_h0[1 - p][bb * HIDDEN + 4 * g + u] = hn;
        }
        grid_barrier(NCTA);

        // ======== layer 1: z1 = [h0_new, h1_prev] @ W1 + b1 ========
        load_hs(hs, g_h0[1 - p]);
        load_ws(ws, W1, g);
        __syncthreads();
        a0 = bias1.x; a1 = bias1.y; a2 = bias1.z; a3 = bias1.w;
        gemm512(&a0, &a1, &a2, &a3, hs + b * HSP, ws4, cg);
        __syncthreads();                       // done reading hs/ws before reload

        load_hs(hs, g_h1[p]);
        load_ws(ws, W1 + (size_t)512 * GATES, g);
        __syncthreads();
        gemm512(&a0, &a1, &a2, &a3, hs + b * HSP, ws4, cg);

        zs[b * ZSP + cg * 4 + 0] = a0;
        zs[b * ZSP + cg * 4 + 1] = a1;
        zs[b * ZSP + cg * 4 + 2] = a2;
        zs[b * ZSP + cg * 4 + 3] = a3;
        __syncthreads();
        {   // cell update (layer 1)
            const int bb = tid >> 2, u = tid & 3;
            float zi = zs[bb * ZSP +      u];
            float zj = zs[bb * ZSP +  4 + u];
            float zf = zs[bb * ZSP +  8 + u];
            float zo = zs[bb * ZSP + 12 + u];
            float c  = cs[BATCH * 4 + tid];
            float cn = c * sigf(zf + 1.0f) + sigf(zi) * tanhf(zj);
            float hn = tanhf(cn) * sigf(zo);
            cs[BATCH * 4 + tid] = cn;
            g_h1[1 - p][bb * HIDDEN + 4 * g + u] = hn;
        }
        grid_barrier(NCTA);
    }

    // ======== head: feats = h1@Wd+bd ; two softmaxes ========
    // Last step t=127 (p=1) wrote g_h1[0].
    if (g == 0 && tid < BATCH) {
        const float* h = g_h1[0] + tid * HIDDEN;
        float f0 = bd[0], f1 = bd[1];
        for (int k = 0; k < HIDDEN; k += 4) {
            float4 hv = __ldcg((const float4*)(h + k));
            f0 = fmaf(hv.x, Wd[2 * (k + 0) + 0], f0); f1 = fmaf(hv.x, Wd[2 * (k + 0) + 1], f1);
            f0 = fmaf(hv.y, Wd[2 * (k + 1) + 0], f0); f1 = fmaf(hv.y, Wd[2 * (k + 1) + 1], f1);
            f0 = fmaf(hv.z, Wd[2 * (k + 2) + 0], f0); f1 = fmaf(hv.z, Wd[2 * (k + 2) + 1], f1);
            f0 = fmaf(hv.w, Wd[2 * (k + 3) + 0], f0); f1 = fmaf(hv.w, Wd[2 * (k + 3) + 1], f1);
        }
        // pred_pe = softmax(feats @ Wpe + bpe)   (Wpe row-major [2][2])
        float l0 = bpe[0] + f0 * Wpe[0] + f1 * Wpe[2];
        float l1 = bpe[1] + f0 * Wpe[1] + f1 * Wpe[3];
        float m  = fmaxf(l0, l1);
        float e0 = __expf(l0 - m), e1 = __expf(l1 - m);
        float inv = 1.0f / (e0 + e1);
        out[tid * 2 + 0] = e0 * inv;
        out[tid * 2 + 1] = e1 * inv;
        // pred_burden = softmax(feats @ Wbur + bbur)   (Wbur row-major [2][5])
        float lb[5], mb = -1e30f;
#pragma unroll
        for (int c5 = 0; c5 < 5; c5++) {
            lb[c5] = bbur[c5] + f0 * Wbur[c5] + f1 * Wbur[5 + c5];
            mb = fmaxf(mb, lb[c5]);
        }
        float s = 0.0f;
#pragma unroll
        for (int c5 = 0; c5 < 5; c5++) { lb[c5] = __expf(lb[c5] - mb); s += lb[c5]; }
        float invs = 1.0f / s;
#pragma unroll
        for (int c5 = 0; c5 < 5; c5++) out[BATCH * 2 + tid * 5 + c5] = lb[c5] * invs;
    }
}

// ---------------- launch ------------------------------------------------------
extern "C" void kernel_launch(void* const* d_in, const int* in_sizes, int n_in,
                              void* d_out, int out_size)
{
    const int*   x    = (const int*)  d_in[0];
    const float* emb  = (const float*)d_in[1];
    const float* W0   = (const float*)d_in[2];
    const float* b0   = (const float*)d_in[3];
    const float* W1   = (const float*)d_in[4];
    const float* b1   = (const float*)d_in[5];
    const float* Wd   = (const float*)d_in[6];
    const float* bd   = (const float*)d_in[7];
    const float* Wpe  = (const float*)d_in[8];
    const float* bpe  = (const float*)d_in[9];
    const float* Wbur = (const float*)d_in[10];
    const float* bbur = (const float*)d_in[11];
    float* out = (float*)d_out;

    cudaFuncSetAttribute(lstm_persistent,
                         cudaFuncAttributeMaxDynamicSharedMemorySize, SMEM_BYTES);

    dim3 pgrid(SEQ * BATCH / 64, GATES / 64);
    xproj_kernel<<<pgrid, 256>>>(x, emb, W0);
    lstm_persistent<<<NCTA, NTHR, SMEM_BYTES>>>(W0, b0, W1, b1, Wd, bd,
                                                Wpe, bpe, Wbur, bbur, out);
}

// round 2
// speedup vs baseline: 2.3459x; 2.3459x over previous
#include <cuda_runtime.h>
#include <math.h>

#define VOCAB  50000
#define EMBED  300
#define HIDDEN 512
#define BATCH  64
#define SEQ    128
#define GATES  2048   // 4*HIDDEN

#define NCTA 128
#define NTHR 512      // 16 warps

typedef unsigned long long u64;

// ---------------- persistent device scratch ----------------------------------
__device__ __align__(16) float g_xproj[(size_t)SEQ * BATCH * GATES]; // 64 MB
__device__ __align__(16) float g_h0t[2][HIDDEN * BATCH];             // transposed [k][b]
__device__ __align__(16) float g_h1t[2][HIDDEN * BATCH];
__device__ unsigned g_bar_count;
__device__ unsigned g_bar_gen;

// ---------------- helpers ----------------------------------------------------
__device__ __forceinline__ float sigf(float x) { return 1.0f / (1.0f + __expf(-x)); }

#define FMA2(d, a, b) asm("fma.rn.f32x2 %0, %1, %2, %0;" : "+l"(d) : "l"(a), "l"(b))
#define PACK1(d, s)   asm("mov.b64 %0, {%1, %1};" : "=l"(d) : "r"(__float_as_uint(s)))
#define PACK2(d, lo, hi) asm("mov.b64 %0, {%1, %2};" : "=l"(d) \
                             : "r"(__float_as_uint(lo)), "r"(__float_as_uint(hi)))

__device__ __forceinline__ void grid_barrier(unsigned nb)
{
    __syncthreads();
    if (threadIdx.x == 0) {
        __threadfence();
        unsigned gen = *((volatile unsigned*)&g_bar_gen);
        unsigned t   = atomicAdd(&g_bar_count, 1u);
        if (t == nb - 1u) {
            g_bar_count = 0u;
            __threadfence();
            atomicAdd(&g_bar_gen, 1u);
        } else {
            while (*((volatile unsigned*)&g_bar_gen) == gen) { }
        }
        __threadfence();
    }
    __syncthreads();
}

// ---------------- phase 1: xproj[t][b][:] = emb[x[b,t]] @ W0[0:300,:] --------
#define PK 20
__global__ void __launch_bounds__(256) xproj_kernel(const int* __restrict__ x,
                                                    const float* __restrict__ emb,
                                                    const float* __restrict__ W0)
{
    __shared__ float Ast[PK][68];
    __shared__ float Bs[PK][68];
    __shared__ int   toks[64];

    const int rb  = blockIdx.x * 64;   // row = t*64 + b
    const int cb  = blockIdx.y * 64;
    const int tid = threadIdx.x;

    if (tid < 64) {
        int r = rb + tid;
        toks[tid] = x[(r & 63) * SEQ + (r >> 6)];
    }
    __syncthreads();

    const int ty = tid >> 4, tx = tid & 15;
    float c[4][4] = {};

    for (int e0 = 0; e0 < EMBED; e0 += PK) {
        for (int i = tid; i < 64 * PK; i += 256) {
            int m = i / PK, e = i - m * PK;
            Ast[e][m] = emb[(size_t)toks[m] * EMBED + e0 + e];
        }
        for (int i = tid; i < PK * 64; i += 256) {
            int e = i >> 6, n = i & 63;
            Bs[e][n] = W0[(size_t)(e0 + e) * GATES + cb + n];
        }
        __syncthreads();
#pragma unroll
        for (int k = 0; k < PK; k++) {
            float4 av = *(const float4*)&Ast[k][ty * 4];
            float4 bv = *(const float4*)&Bs[k][tx * 4];
            c[0][0] = fmaf(av.x, bv.x, c[0][0]); c[0][1] = fmaf(av.x, bv.y, c[0][1]);
            c[0][2] = fmaf(av.x, bv.z, c[0][2]); c[0][3] = fmaf(av.x, bv.w, c[0][3]);
            c[1][0] = fmaf(av.y, bv.x, c[1][0]); c[1][1] = fmaf(av.y, bv.y, c[1][1]);
            c[1][2] = fmaf(av.y, bv.z, c[1][2]); c[1][3] = fmaf(av.y, bv.w, c[1][3]);
            c[2][0] = fmaf(av.z, bv.x, c[2][0]); c[2][1] = fmaf(av.z, bv.y, c[2][1]);
            c[2][2] = fmaf(av.z, bv.z, c[2][2]); c[2][3] = fmaf(av.z, bv.w, c[2][3]);
            c[3][0] = fmaf(av.w, bv.x, c[3][0]); c[3][1] = fmaf(av.w, bv.y, c[3][1]);
            c[3][2] = fmaf(av.w, bv.z, c[3][2]); c[3][3] = fmaf(av.w, bv.w, c[3][3]);
        }
        __syncthreads();
    }
#pragma unroll
    for (int ii = 0; ii < 4; ii++) {
        size_t row = (size_t)(rb + ty * 4 + ii);
        *(float4*)(g_xproj + row * GATES + cb + tx * 4) =
            make_float4(c[ii][0], c[ii][1], c[ii][2], c[ii][3]);
    }
}

// ---------------- phase 2: persistent recurrent kernel -----------------------
// CTA g owns hidden units 4g..4g+3 of both layers: cols {q*512 + 4g + u}.
// Local col index c = q*4 + u  (q = gate i/j/f/o, u = unit-in-CTA).
// wsm[k][c]: rows 0..511 = W0rec (W0[300+k]), rows 512..1535 = W1[k].
// Warp tile = full 64 batch x 16 col output; 16 warps split K (32 k each).
// Per-thread tile: 8 batches (as 4 f32x2 pairs) x 4 cols. lane = br*4 + cc.
#define WSM_FLOATS  (1536 * 16)          // 24576
#define HBUF_FLOATS (HIDDEN * BATCH)     // 32768 (h stage buffer; reused as reduce buffer)
#define SMEM_BYTES  ((WSM_FLOATS + HBUF_FLOATS) * 4)   // 229376

__global__ void __launch_bounds__(NTHR, 1) lstm_persistent(
    const float* __restrict__ W0,  const float* __restrict__ b0,
    const float* __restrict__ W1,  const float* __restrict__ b1,
    const float* __restrict__ Wd,  const float* __restrict__ bd,
    const float* __restrict__ Wpe, const float* __restrict__ bpe,
    const float* __restrict__ Wbur,const float* __restrict__ bbur,
    float* __restrict__ out)
{
    extern __shared__ float sm[];
    float* wsm  = sm;                 // [1536][16]
    float* hbuf = sm + WSM_FLOATS;    // [512][64] staged h  /  [16][2048] partials

    const int g    = blockIdx.x;
    const int tid  = threadIdx.x;
    const int wid  = tid >> 5;
    const int lane = tid & 31;
    const int br   = lane >> 2;       // batch group 0..7  (batches br*8 .. br*8+7)
    const int cc   = lane & 3;        // col group 0..3    (cols cc*4 .. cc*4+3)

    // ---- stage weights ONCE ----
    for (int idx = tid; idx < WSM_FLOATS; idx += NTHR) {
        int k = idx >> 4, c = idx & 15;
        int col = (c >> 2) * HIDDEN + 4 * g + (c & 3);
        wsm[idx] = (k < 512) ? W0[(size_t)(EMBED + k) * GATES + col]
                             : W1[(size_t)(k - 512) * GATES + col];
    }

    const int colb = cc * HIDDEN + 4 * g;          // first of this thread's 4 cols
    const float4 bias0v = *(const float4*)(b0 + colb);
    const float4 bias1v = *(const float4*)(b1 + colb);

    // ---- prologue: h0(0) = cell(xproj(0)+b0, c=0);  h1(-1) = 0 ----
    float c0st = 0.0f, c1st = 0.0f;
    if (tid < 256) {
        int b = tid >> 2, u = tid & 3;
        float z[4];
#pragma unroll
        for (int q = 0; q < 4; q++) {
            int col = q * HIDDEN + 4 * g + u;
            z[q] = g_xproj[(size_t)b * GATES + col] + b0[col];
        }
        c0st = sigf(z[0]) * tanhf(z[1]);           // c_prev = 0
        float h0n = tanhf(c0st) * sigf(z[3]);
        g_h0t[0][(4 * g + u) * BATCH + b] = h0n;
        g_h1t[1][(4 * g + u) * BATCH + b] = 0.0f;
    }
    grid_barrier(NCTA);

    for (int t = 0; t < SEQ; t++) {
        const int pA = t & 1;
        const int tn = (t + 1 < SEQ) ? (t + 1) : (SEQ - 1);

        // ---- stage h0(t) (transposed layout: straight copy) ----
        {
            const float4* s4 = (const float4*)g_h0t[pA];
            float4* d4 = (float4*)hbuf;
            for (int i = tid; i < HBUF_FLOATS / 4; i += NTHR) d4[i] = __ldcg(s4 + i);
        }
        __syncthreads();

        // ---- init accumulators ----
        u64 accA[16], accB[16];
        if (wid == 0) {
            u64 pb1x, pb1y, pb1z, pb1w;
            PACK1(pb1x, bias1v.x); PACK1(pb1y, bias1v.y);
            PACK1(pb1z, bias1v.z); PACK1(pb1w, bias1v.w);
#pragma unroll
            for (int i = 0; i < 4; i++) {
                accA[i * 4 + 0] = pb1x; accA[i * 4 + 1] = pb1y;
                accA[i * 4 + 2] = pb1z; accA[i * 4 + 3] = pb1w;
            }
#pragma unroll
            for (int i = 0; i < 4; i++) {
                float4 xe = __ldcg((const float4*)(g_xproj +
                             ((size_t)tn * BATCH + br * 8 + 2 * i) * GATES + colb));
                float4 xo = __ldcg((const float4*)(g_xproj +
                             ((size_t)tn * BATCH + br * 8 + 2 * i + 1) * GATES + colb));
                PACK2(accB[i * 4 + 0], xe.x + bias0v.x, xo.x + bias0v.x);
                PACK2(accB[i * 4 + 1], xe.y + bias0v.y, xo.y + bias0v.y);
                PACK2(accB[i * 4 + 2], xe.z + bias0v.z, xo.z + bias0v.z);
                PACK2(accB[i * 4 + 3], xe.w + bias0v.w, xo.w + bias0v.w);
            }
        } else {
#pragma unroll
            for (int i = 0; i < 16; i++) { accA[i] = 0ull; accB[i] = 0ull; }
        }

        // ---- phase 1: k in [wid*32, wid*32+32): A += h0*W1[k], B += h0*W0rec[k]
        {
            const float* wA = wsm + (512 + wid * 32) * 16;
            const float* wB = wsm + (wid * 32) * 16;
            const u64*   hp = (const u64*)hbuf + (wid * 32) * 32 + br * 4;
#pragma unroll 4
            for (int kk = 0; kk < 32; kk++) {
                u64 h0p = hp[0], h1p = hp[1], h2p = hp[2], h3p = hp[3];
                float4 wa = ((const float4*)wA)[cc];
                float4 wb = ((const float4*)wB)[cc];
                u64 pa0, pa1, pa2, pa3, pb0, pb1, pb2, pb3;
                PACK1(pa0, wa.x); PACK1(pa1, wa.y); PACK1(pa2, wa.z); PACK1(pa3, wa.w);
                PACK1(pb0, wb.x); PACK1(pb1, wb.y); PACK1(pb2, wb.z); PACK1(pb3, wb.w);
                FMA2(accA[0],  h0p, pa0); FMA2(accA[1],  h0p, pa1);
                FMA2(accA[2],  h0p, pa2); FMA2(accA[3],  h0p, pa3);
                FMA2(accA[4],  h1p, pa0); FMA2(accA[5],  h1p, pa1);
                FMA2(accA[6],  h1p, pa2); FMA2(accA[7],  h1p, pa3);
                FMA2(accA[8],  h2p, pa0); FMA2(accA[9],  h2p, pa1);
                FMA2(accA[10], h2p, pa2); FMA2(accA[11], h2p, pa3);
                FMA2(accA[12], h3p, pa0); FMA2(accA[13], h3p, pa1);
                FMA2(accA[14], h3p, pa2); FMA2(accA[15], h3p, pa3);
                FMA2(accB[0],  h0p, pb0); FMA2(accB[1],  h0p, pb1);
                FMA2(accB[2],  h0p, pb2); FMA2(accB[3],  h0p, pb3);
                FMA2(accB[4],  h1p, pb0); FMA2(accB[5],  h1p, pb1);
                FMA2(accB[6],  h1p, pb2); FMA2(accB[7],  h1p, pb3);
                FMA2(accB[8],  h2p, pb0); FMA2(accB[9],  h2p, pb1);
                FMA2(accB[10], h2p, pb2); FMA2(accB[11], h2p, pb3);
                FMA2(accB[12], h3p, pb0); FMA2(accB[13], h3p, pb1);
                FMA2(accB[14], h3p, pb2); FMA2(accB[15], h3p, pb3);
                hp += 32; wA += 16; wB += 16;
            }
        }
        __syncthreads();

        // ---- stage h1(t-1) ----
        {
            const float4* s4 = (const float4*)g_h1t[1 - pA];
            float4* d4 = (float4*)hbuf;
            for (int i = tid; i < HBUF_FLOATS / 4; i += NTHR) d4[i] = __ldcg(s4 + i);
        }
        __syncthreads();

        // ---- phase 2: A += h1 * W1[512+k] ----
        {
            const float* wC = wsm + (1024 + wid * 32) * 16;
            const u64*   hp = (const u64*)hbuf + (wid * 32) * 32 + br * 4;
#pragma unroll 4
            for (int kk = 0; kk < 32; kk++) {
                u64 h0p = hp[0], h1p = hp[1], h2p = hp[2], h3p = hp[3];
                float4 wc = ((const float4*)wC)[cc];
                u64 pc0, pc1, pc2, pc3;
                PACK1(pc0, wc.x); PACK1(pc1, wc.y); PACK1(pc2, wc.z); PACK1(pc3, wc.w);
                FMA2(accA[0],  h0p, pc0); FMA2(accA[1],  h0p, pc1);
                FMA2(accA[2],  h0p, pc2); FMA2(accA[3],  h0p, pc3);
                FMA2(accA[4],  h1p, pc0); FMA2(accA[5],  h1p, pc1);
                FMA2(accA[6],  h1p, pc2); FMA2(accA[7],  h1p, pc3);
                FMA2(accA[8],  h2p, pc0); FMA2(accA[9],  h2p, pc1);
                FMA2(accA[10], h2p, pc2); FMA2(accA[11], h2p, pc3);
                FMA2(accA[12], h3p, pc0); FMA2(accA[13], h3p, pc1);
                FMA2(accA[14], h3p, pc2); FMA2(accA[15], h3p, pc3);
                hp += 32; wC += 16;
            }
        }
        __syncthreads();

        // ---- write partials: red[wid][c][b] as u64 (batch pairs adjacent) ----
        {
            u64* redw = (u64*)(hbuf + wid * 2048);
#pragma unroll
            for (int i = 0; i < 4; i++) {
#pragma unroll
                for (int j = 0; j < 4; j++) {
                    redw[(cc * 4 + j) * 32 + br * 4 + i]       = accA[i * 4 + j];
                    redw[512 + (cc * 4 + j) * 32 + br * 4 + i] = accB[i * 4 + j];
                }
            }
        }
        __syncthreads();

        // ---- reduce over 16 warps ----
        {
            float4* r4 = (float4*)hbuf;
            float4 s = r4[tid];
#pragma unroll
            for (int w = 1; w < 16; w++) {
                float4 v = r4[w * 512 + tid];
                s.x += v.x; s.y += v.y; s.z += v.z; s.w += v.w;
            }
            r4[tid] = s;
        }
        __syncthreads();

        // ---- cell update: z1 at hbuf[(q*4+u)*64 + b], z0 at +1024 ----
        if (tid < 256) {
            int b = tid >> 2, u = tid & 3;
            float zi1 = hbuf[(0 + u) * 64 + b];
            float zj1 = hbuf[(4 + u) * 64 + b];
            float zf1 = hbuf[(8 + u) * 64 + b];
            float zo1 = hbuf[(12 + u) * 64 + b];
            float zi0 = hbuf[1024 + (0 + u) * 64 + b];
            float zj0 = hbuf[1024 + (4 + u) * 64 + b];
            float zf0 = hbuf[1024 + (8 + u) * 64 + b];
            float zo0 = hbuf[1024 + (12 + u) * 64 + b];
            c1st = c1st * sigf(zf1 + 1.0f) + sigf(zi1) * tanhf(zj1);
            float h1n = tanhf(c1st) * sigf(zo1);
            c0st = c0st * sigf(zf0 + 1.0f) + sigf(zi0) * tanhf(zj0);
            float h0n = tanhf(c0st) * sigf(zo0);
            g_h1t[pA][(4 * g + u) * BATCH + b]     = h1n;   // h1(t)
            g_h0t[1 - pA][(4 * g + u) * BATCH + b] = h0n;   // h0(t+1)
        }
        grid_barrier(NCTA);
    }

    // ---- head: CTA 0, thread b.  h1(127) lives in g_h1t[1] (127&1). ----
    if (g == 0 && tid < BATCH) {
        float f0 = bd[0], f1 = bd[1];
#pragma unroll 4
        for (int k = 0; k < HIDDEN; k++) {
            float hv = __ldcg(&g_h1t[1][k * BATCH + tid]);
            f0 = fmaf(hv, Wd[2 * k + 0], f0);
            f1 = fmaf(hv, Wd[2 * k + 1], f1);
        }
        float l0 = bpe[0] + f0 * Wpe[0] + f1 * Wpe[2];
        float l1 = bpe[1] + f0 * Wpe[1] + f1 * Wpe[3];
        float m  = fmaxf(l0, l1);
        float e0 = __expf(l0 - m), e1 = __expf(l1 - m);
        float inv = 1.0f / (e0 + e1);
        out[tid * 2 + 0] = e0 * inv;
        out[tid * 2 + 1] = e1 * inv;
        float lb[5], mb = -1e30f;
#pragma unroll
        for (int c5 = 0; c5 < 5; c5++) {
            lb[c5] = bbur[c5] + f0 * Wbur[c5] + f1 * Wbur[5 + c5];
            mb = fmaxf(mb, lb[c5]);
        }
        float s = 0.0f;
#pragma unroll
        for (int c5 = 0; c5 < 5; c5++) { lb[c5] = __expf(lb[c5] - mb); s += lb[c5]; }
        float invs = 1.0f / s;
#pragma unroll
        for (int c5 = 0; c5 < 5; c5++) out[BATCH * 2 + tid * 5 + c5] = lb[c5] * invs;
    }
}

// ---------------- launch ------------------------------------------------------
extern "C" void kernel_launch(void* const* d_in, const int* in_sizes, int n_in,
                              void* d_out, int out_size)
{
    const int*   x    = (const int*)  d_in[0];
    const float* emb  = (const float*)d_in[1];
    const float* W0   = (const float*)d_in[2];
    const float* b0   = (const float*)d_in[3];
    const float* W1   = (const float*)d_in[4];
    const float* b1   = (const float*)d_in[5];
    const float* Wd   = (const float*)d_in[6];
    const float* bd   = (const float*)d_in[7];
    const float* Wpe  = (const float*)d_in[8];
    const float* bpe  = (const float*)d_in[9];
    const float* Wbur = (const float*)d_in[10];
    const float* bbur = (const float*)d_in[11];
    float* out = (float*)d_out;

    cudaFuncSetAttribute(lstm_persistent,
                         cudaFuncAttributeMaxDynamicSharedMemorySize, SMEM_BYTES);

    dim3 pgrid(SEQ * BATCH / 64, GATES / 64);
    xproj_kernel<<<pgrid, 256>>>(x, emb, W0);
    lstm_persistent<<<NCTA, NTHR, SMEM_BYTES>>>(W0, b0, W1, b1, Wd, bd,
                                                Wpe, bpe, Wbur, bbur, out);
}

// round 4
// speedup vs baseline: 2.4547x; 1.0464x over previous
#include <cuda_runtime.h>
#include <math.h>

#define VOCAB  50000
#define EMBED  300
#define HIDDEN 512
#define BATCH  64
#define SEQ    128
#define GATES  2048   // 4*HIDDEN

#define NCTA 128
#define NTHR 512      // 16 warps

typedef unsigned long long u64;

// ---------------- persistent device scratch ----------------------------------
__device__ __align__(16) float g_xproj[(size_t)SEQ * BATCH * GATES]; // 64 MB
__device__ __align__(16) float g_h0t[2][HIDDEN * BATCH];             // transposed [k][b]
__device__ __align__(16) float g_h1t[2][HIDDEN * BATCH];
__device__ unsigned g_bar_count;
__device__ unsigned g_bar_gen;

// ---------------- helpers ----------------------------------------------------
__device__ __forceinline__ float sigf(float x) { return 1.0f / (1.0f + __expf(-x)); }

#define FMA2(d, a, b) asm("fma.rn.f32x2 %0, %1, %2, %0;" : "+l"(d) : "l"(a), "l"(b))
#define PACK1(d, s)   asm("mov.b64 %0, {%1, %1};" : "=l"(d) : "r"(__float_as_uint(s)))
#define PACK2(d, lo, hi) asm("mov.b64 %0, {%1, %2};" : "=l"(d) \
                             : "r"(__float_as_uint(lo)), "r"(__float_as_uint(hi)))

__device__ __forceinline__ void grid_barrier(unsigned nb)
{
    __syncthreads();
    if (threadIdx.x == 0) {
        __threadfence();
        unsigned gen = *((volatile unsigned*)&g_bar_gen);
        unsigned t   = atomicAdd(&g_bar_count, 1u);
        if (t == nb - 1u) {
            g_bar_count = 0u;
            __threadfence();
            atomicAdd(&g_bar_gen, 1u);
        } else {
            while (*((volatile unsigned*)&g_bar_gen) == gen) { }
        }
        __threadfence();
    }
    __syncthreads();
}

// ---------------- phase 1: xproj[t][b][:] = emb[x[b,t]] @ W0[0:300,:] --------
#define PK 20
__global__ void __launch_bounds__(256) xproj_kernel(const int* __restrict__ x,
                                                    const float* __restrict__ emb,
                                                    const float* __restrict__ W0)
{
    __shared__ float Ast[PK][68];
    __shared__ float Bs[PK][68];
    __shared__ int   toks[64];

    const int rb  = blockIdx.x * 64;   // row = t*64 + b
    const int cb  = blockIdx.y * 64;
    const int tid = threadIdx.x;

    if (tid < 64) {
        int r = rb + tid;
        toks[tid] = x[(r & 63) * SEQ + (r >> 6)];
    }
    __syncthreads();

    const int ty = tid >> 4, tx = tid & 15;
    float c[4][4] = {};

    for (int e0 = 0; e0 < EMBED; e0 += PK) {
        for (int i = tid; i < 64 * PK; i += 256) {
            int m = i / PK, e = i - m * PK;
            Ast[e][m] = emb[(size_t)toks[m] * EMBED + e0 + e];
        }
        for (int i = tid; i < PK * 64; i += 256) {
            int e = i >> 6, n = i & 63;
            Bs[e][n] = W0[(size_t)(e0 + e) * GATES + cb + n];
        }
        __syncthreads();
#pragma unroll
        for (int k = 0; k < PK; k++) {
            float4 av = *(const float4*)&Ast[k][ty * 4];
            float4 bv = *(const float4*)&Bs[k][tx * 4];
            c[0][0] = fmaf(av.x, bv.x, c[0][0]); c[0][1] = fmaf(av.x, bv.y, c[0][1]);
            c[0][2] = fmaf(av.x, bv.z, c[0][2]); c[0][3] = fmaf(av.x, bv.w, c[0][3]);
            c[1][0] = fmaf(av.y, bv.x, c[1][0]); c[1][1] = fmaf(av.y, bv.y, c[1][1]);
            c[1][2] = fmaf(av.y, bv.z, c[1][2]); c[1][3] = fmaf(av.y, bv.w, c[1][3]);
            c[2][0] = fmaf(av.z, bv.x, c[2][0]); c[2][1] = fmaf(av.z, bv.y, c[2][1]);
            c[2][2] = fmaf(av.z, bv.z, c[2][2]); c[2][3] = fmaf(av.z, bv.w, c[2][3]);
            c[3][0] = fmaf(av.w, bv.x, c[3][0]); c[3][1] = fmaf(av.w, bv.y, c[3][1]);
            c[3][2] = fmaf(av.w, bv.z, c[3][2]); c[3][3] = fmaf(av.w, bv.w, c[3][3]);
        }
        __syncthreads();
    }
#pragma unroll
    for (int ii = 0; ii < 4; ii++) {
        size_t row = (size_t)(rb + ty * 4 + ii);
        *(float4*)(g_xproj + row * GATES + cb + tx * 4) =
            make_float4(c[ii][0], c[ii][1], c[ii][2], c[ii][3]);
    }
}

// ---------------- phase 2: persistent recurrent kernel -----------------------
// CTA g owns hidden units 4g..4g+3 of both layers: cols {q*512 + 4g + u}.
// wsm[k][c]: rows 0..511 = W0rec (W0[300+k]), rows 512..1535 = W1[k].
// 16 warps split K (32 k each).  Per-thread: 8 batches (4 f32x2) x 4 cols.
// KEY: each warp stages ONLY its own k-slice of h -> warp-private region
// hbuf[wid*2048 .. +2048), which doubles as its reduction-partials region.
// No block sync between staging and FMA; 2 syncthreads/step total.
#define WSM_FLOATS  (1536 * 16)          // 24576
#define HBUF_FLOATS (HIDDEN * BATCH)     // 32768
#define SMEM_BYTES  ((WSM_FLOATS + HBUF_FLOATS) * 4)   // 229376

__global__ void __launch_bounds__(NTHR, 1) lstm_persistent(
    const float* __restrict__ W0,  const float* __restrict__ b0,
    const float* __restrict__ W1,  const float* __restrict__ b1,
    const float* __restrict__ Wd,  const float* __restrict__ bd,
    const float* __restrict__ Wpe, const float* __restrict__ bpe,
    const float* __restrict__ Wbur,const float* __restrict__ bbur,
    float* __restrict__ out)
{
    extern __shared__ float sm[];
    float* wsm  = sm;                 // [1536][16]
    float* hbuf = sm + WSM_FLOATS;    // [512][64] h slices  /  [16][2048] partials

    const int g    = blockIdx.x;
    const int tid  = threadIdx.x;
    const int wid  = tid >> 5;
    const int lane = tid & 31;
    const int br   = lane >> 2;       // batch group 0..7
    const int cc   = lane & 3;        // col group 0..3

    // ---- stage weights ONCE ----
    for (int idx = tid; idx < WSM_FLOATS; idx += NTHR) {
        int k = idx >> 4, c = idx & 15;
        int col = (c >> 2) * HIDDEN + 4 * g + (c & 3);
        wsm[idx] = (k < 512) ? W0[(size_t)(EMBED + k) * GATES + col]
                             : W1[(size_t)(k - 512) * GATES + col];
    }

    const int colb = cc * HIDDEN + 4 * g;
    const float4 bias0v = *(const float4*)(b0 + colb);
    const float4 bias1v = *(const float4*)(b1 + colb);

    // warp-private stage pointers (slice = k in [wid*32, wid*32+32) x 64 b)
    float4*       slice_d4 = (float4*)hbuf + wid * 512;

    // ---- prologue: h0(0) = cell(xproj(0)+b0, c=0);  h1(-1) = 0 ----
    float c0st = 0.0f, c1st = 0.0f;
    if (tid < 256) {
        int b = tid >> 2, u = tid & 3;
        float z[4];
#pragma unroll
        for (int q = 0; q < 4; q++) {
            int col = q * HIDDEN + 4 * g + u;
            z[q] = g_xproj[(size_t)b * GATES + col] + b0[col];
        }
        c0st = sigf(z[0]) * tanhf(z[1]);           // c_prev = 0
        float h0n = tanhf(c0st) * sigf(z[3]);
        g_h0t[0][(4 * g + u) * BATCH + b] = h0n;
        g_h1t[1][(4 * g + u) * BATCH + b] = 0.0f;
    }
    grid_barrier(NCTA);

    for (int t = 0; t < SEQ; t++) {
        const int pA = t & 1;
        const int tn = (t + 1 < SEQ) ? (t + 1) : (SEQ - 1);

        // ---- stage h0(t) slice (warp-private, no block sync) ----
        {
            const float4* s4 = (const float4*)g_h0t[pA] + wid * 512;
#pragma unroll
            for (int i = lane; i < 512; i += 32) slice_d4[i] = __ldcg(s4 + i);
        }
        __syncwarp();

        // ---- init accumulators ----
        u64 accA[16], accB[16];
        if (wid == 0) {
            u64 pb1x, pb1y, pb1z, pb1w;
            PACK1(pb1x, bias1v.x); PACK1(pb1y, bias1v.y);
            PACK1(pb1z, bias1v.z); PACK1(pb1w, bias1v.w);
#pragma unroll
            for (int i = 0; i < 4; i++) {
                accA[i * 4 + 0] = pb1x; accA[i * 4 + 1] = pb1y;
                accA[i * 4 + 2] = pb1z; accA[i * 4 + 3] = pb1w;
            }
#pragma unroll
            for (int i = 0; i < 4; i++) {
                float4 xe = __ldcg((const float4*)(g_xproj +
                             ((size_t)tn * BATCH + br * 8 + 2 * i) * GATES + colb));
                float4 xo = __ldcg((const float4*)(g_xproj +
                             ((size_t)tn * BATCH + br * 8 + 2 * i + 1) * GATES + colb));
                PACK2(accB[i * 4 + 0], xe.x + bias0v.x, xo.x + bias0v.x);
                PACK2(accB[i * 4 + 1], xe.y + bias0v.y, xo.y + bias0v.y);
                PACK2(accB[i * 4 + 2], xe.z + bias0v.z, xo.z + bias0v.z);
                PACK2(accB[i * 4 + 3], xe.w + bias0v.w, xo.w + bias0v.w);
            }
        } else {
#pragma unroll
            for (int i = 0; i < 16; i++) { accA[i] = 0ull; accB[i] = 0ull; }
        }

        // ---- phase 1: k in warp slice: A += h0*W1[k], B += h0*W0rec[k] ----
        {
            const float* wA = wsm + (512 + wid * 32) * 16;
            const float* wB = wsm + (wid * 32) * 16;
            const u64*   hp = (const u64*)hbuf + (wid * 32) * 32 + br * 4;
#pragma unroll 4
            for (int kk = 0; kk < 32; kk++) {
                u64 h0p = hp[0], h1p = hp[1], h2p = hp[2], h3p = hp[3];
                float4 wa = ((const float4*)wA)[cc];
                float4 wb = ((const float4*)wB)[cc];
                u64 pa0, pa1, pa2, pa3, pb0, pb1, pb2, pb3;
                PACK1(pa0, wa.x); PACK1(pa1, wa.y); PACK1(pa2, wa.z); PACK1(pa3, wa.w);
                PACK1(pb0, wb.x); PACK1(pb1, wb.y); PACK1(pb2, wb.z); PACK1(pb3, wb.w);
                FMA2(accA[0],  h0p, pa0); FMA2(accA[1],  h0p, pa1);
                FMA2(accA[2],  h0p, pa2); FMA2(accA[3],  h0p, pa3);
                FMA2(accA[4],  h1p, pa0); FMA2(accA[5],  h1p, pa1);
                FMA2(accA[6],  h1p, pa2); FMA2(accA[7],  h1p, pa3);
                FMA2(accA[8],  h2p, pa0); FMA2(accA[9],  h2p, pa1);
                FMA2(accA[10], h2p, pa2); FMA2(accA[11], h2p, pa3);
                FMA2(accA[12], h3p, pa0); FMA2(accA[13], h3p, pa1);
                FMA2(accA[14], h3p, pa2); FMA2(accA[15], h3p, pa3);
                FMA2(accB[0],  h0p, pb0); FMA2(accB[1],  h0p, pb1);
                FMA2(accB[2],  h0p, pb2); FMA2(accB[3],  h0p, pb3);
                FMA2(accB[4],  h1p, pb0); FMA2(accB[5],  h1p, pb1);
                FMA2(accB[6],  h1p, pb2); FMA2(accB[7],  h1p, pb3);
                FMA2(accB[8],  h2p, pb0); FMA2(accB[9],  h2p, pb1);
                FMA2(accB[10], h2p, pb2); FMA2(accB[11], h2p, pb3);
                FMA2(accB[12], h3p, pb0); FMA2(accB[13], h3p, pb1);
                FMA2(accB[14], h3p, pb2); FMA2(accB[15], h3p, pb3);
                hp += 32; wA += 16; wB += 16;
            }
        }

        // ---- stage h1(t-1) slice over own region (warp-private) ----
        {
            const float4* s4 = (const float4*)g_h1t[1 - pA] + wid * 512;
#pragma unroll
            for (int i = lane; i < 512; i += 32) slice_d4[i] = __ldcg(s4 + i);
        }
        __syncwarp();

        // ---- phase 2: A += h1 * W1[512+k] ----
        {
            const float* wC = wsm + (1024 + wid * 32) * 16;
            const u64*   hp = (const u64*)hbuf + (wid * 32) * 32 + br * 4;
#pragma unroll 4
            for (int kk = 0; kk < 32; kk++) {
                u64 h0p = hp[0], h1p = hp[1], h2p = hp[2], h3p = hp[3];
                float4 wc = ((const float4*)wC)[cc];
                u64 pc0, pc1, pc2, pc3;
                PACK1(pc0, wc.x); PACK1(pc1, wc.y); PACK1(pc2, wc.z); PACK1(pc3, wc.w);
                FMA2(accA[0],  h0p, pc0); FMA2(accA[1],  h0p, pc1);
                FMA2(accA[2],  h0p, pc2); FMA2(accA[3],  h0p, pc3);
                FMA2(accA[4],  h1p, pc0); FMA2(accA[5],  h1p, pc1);
                FMA2(accA[6],  h1p, pc2); FMA2(accA[7],  h1p, pc3);
                FMA2(accA[8],  h2p, pc0); FMA2(accA[9],  h2p, pc1);
                FMA2(accA[10], h2p, pc2); FMA2(accA[11], h2p, pc3);
                FMA2(accA[12], h3p, pc0); FMA2(accA[13], h3p, pc1);
                FMA2(accA[14], h3p, pc2); FMA2(accA[15], h3p, pc3);
                hp += 32; wC += 16;
            }
        }
        __syncwarp();

        // ---- write partials into OWN region: red[wid][c][b] as u64 ----
        {
            u64* redw = (u64*)(hbuf + wid * 2048);
#pragma unroll
            for (int i = 0; i < 4; i++) {
#pragma unroll
                for (int j = 0; j < 4; j++) {
                    redw[(cc * 4 + j) * 32 + br * 4 + i]       = accA[i * 4 + j];
                    redw[512 + (cc * 4 + j) * 32 + br * 4 + i] = accB[i * 4 + j];
                }
            }
        }
        __syncthreads();                      // all partials visible

        // ---- reduce over 16 warps into hbuf[0..2048) ----
        {
            float4* r4 = (float4*)hbuf;
            float4 s = r4[tid];
#pragma unroll
            for (int w = 1; w < 16; w++) {
                float4 v = r4[w * 512 + tid];
                s.x += v.x; s.y += v.y; s.z += v.z; s.w += v.w;
            }
            r4[tid] = s;
        }
        __syncthreads();                      // reduced z visible

        // ---- cell update: z1 at hbuf[(q*4+u)*64 + b], z0 at +1024 ----
        if (tid < 256) {
            int b = tid >> 2, u = tid & 3;
            float zi1 = hbuf[(0 + u) * 64 + b];
            float zj1 = hbuf[(4 + u) * 64 + b];
            float zf1 = hbuf[(8 + u) * 64 + b];
            float zo1 = hbuf[(12 + u) * 64 + b];
            float zi0 = hbuf[1024 + (0 + u) * 64 + b];
            float zj0 = hbuf[1024 + (4 + u) * 64 + b];
            float zf0 = hbuf[1024 + (8 + u) * 64 + b];
            float zo0 = hbuf[1024 + (12 + u) * 64 + b];
            c1st = c1st * sigf(zf1 + 1.0f) + sigf(zi1) * tanhf(zj1);
            float h1n = tanhf(c1st) * sigf(zo1);
            c0st = c0st * sigf(zf0 + 1.0f) + sigf(zi0) * tanhf(zj0);
            float h0n = tanhf(c0st) * sigf(zo0);
            g_h1t[pA][(4 * g + u) * BATCH + b]     = h1n;   // h1(t)
            g_h0t[1 - pA][(4 * g + u) * BATCH + b] = h0n;   // h0(t+1)
        }
        grid_barrier(NCTA);
    }

    // ---- head: CTA 0, thread b.  h1(127) lives in g_h1t[1]. ----
    if (g == 0 && tid < BATCH) {
        float f0 = bd[0], f1 = bd[1];
#pragma unroll 4
        for (int k = 0; k < HIDDEN; k++) {
            float hv = __ldcg(&g_h1t[1][k * BATCH + tid]);
            f0 = fmaf(hv, Wd[2 * k + 0], f0);
            f1 = fmaf(hv, Wd[2 * k + 1], f1);
        }
        float l0 = bpe[0] + f0 * Wpe[0] + f1 * Wpe[2];
        float l1 = bpe[1] + f0 * Wpe[1] + f1 * Wpe[3];
        float m  = fmaxf(l0, l1);
        float e0 = __expf(l0 - m), e1 = __expf(l1 - m);
        float inv = 1.0f / (e0 + e1);
        out[tid * 2 + 0] = e0 * inv;
        out[tid * 2 + 1] = e1 * inv;
        float lb[5], mb = -1e30f;
#pragma unroll
        for (int c5 = 0; c5 < 5; c5++) {
            lb[c5] = bbur[c5] + f0 * Wbur[c5] + f1 * Wbur[5 + c5];
            mb = fmaxf(mb, lb[c5]);
        }
        float s = 0.0f;
#pragma unroll
        for (int c5 = 0; c5 < 5; c5++) { lb[c5] = __expf(lb[c5] - mb); s += lb[c5]; }
        float invs = 1.0f / s;
#pragma unroll
        for (int c5 = 0; c5 < 5; c5++) out[BATCH * 2 + tid * 5 + c5] = lb[c5] * invs;
    }
}

// ---------------- launch ------------------------------------------------------
extern "C" void kernel_launch(void* const* d_in, const int* in_sizes, int n_in,
                              void* d_out, int out_size)
{
    const int*   x    = (const int*)  d_in[0];
    const float* emb  = (const float*)d_in[1];
    const float* W0   = (const float*)d_in[2];
    const float* b0   = (const float*)d_in[3];
    const float* W1   = (const float*)d_in[4];
    const float* b1   = (const float*)d_in[5];
    const float* Wd   = (const float*)d_in[6];
    const float* bd   = (const float*)d_in[7];
    const float* Wpe  = (const float*)d_in[8];
    const float* bpe  = (const float*)d_in[9];
    const float* Wbur = (const float*)d_in[10];
    const float* bbur = (const float*)d_in[11];
    float* out = (float*)d_out;

    cudaFuncSetAttribute(lstm_persistent,
                         cudaFuncAttributeMaxDynamicSharedMemorySize, SMEM_BYTES);

    dim3 pgrid(SEQ * BATCH / 64, GATES / 64);
    xproj_kernel<<<pgrid, 256>>>(x, emb, W0);
    lstm_persistent<<<NCTA, NTHR, SMEM_BYTES>>>(W0, b0, W1, b1, Wd, bd,
                                                Wpe, bpe, Wbur, bbur, out);
}